// round 10
// baseline (speedup 1.0000x reference)
#include <cuda_runtime.h>
#include <cuda_fp16.h>
#include <cuda_bf16.h>
#include <cstdint>

#define D 1024
#define NLIN 15
#define MROWS 8192
#define RANK 32
#define GBM 128
#define GBN 64
#define GBK 16
#define SX_STRIDE 132
#define SW_STRIDE 68

// ---------------- device scratch: 33MB total ----------------
__device__ __half g_r1h[MROWS * D];   // 16MB, relu(lin0) in f16 (exact for main path)
__device__ __half g_r2h[MROWS * D];   // 16MB, relu(lin1) in f16
__device__ float  g_t[MROWS * RANK];  // 1MB, lora t = x @ A^T
__device__ int    g_flags[4];         // 0: lora swap, 1: ln swap, 2/3: scales/biases dtype

__device__ __forceinline__ float gld(const float* p, size_t i, size_t n) {
    return (i < n) ? p[i] : 0.f;
}
// f16 parameter fetch tolerant of harness dtype handling (f16 raw / bf16 / f32-promoted)
__device__ __forceinline__ __half fetch_h(const void* p, size_t i, size_t n, int fl) {
    if (i >= n) return __float2half(0.f);
    if (fl == 2) return __float2half(((const float*)p)[i]);
    if (fl == 1) return __float2half(__bfloat162float(((const __nv_bfloat16*)p)[i]));
    return ((const __half*)p)[i];
}
// activation fetch: sel -1 = external x (guarded), 0 = d_out stream, 1/2 = f16 buffers
__device__ __forceinline__ float xfetch(int sel, const float* x, size_t nX,
                                        const float* out, size_t gi) {
    switch (sel) {
        case 1:  return __half2float(g_r1h[gi]);
        case 2:  return __half2float(g_r2h[gi]);
        case 0:  return out[gi];
        default: return (gi < nX) ? x[gi] : 0.f;
    }
}

// ---------------- diagnostic fill (binding failure -> encode info in output) ----------------
__global__ void diag_kernel(float* out, long long n, float val) {
    long long i = (long long)blockIdx.x * blockDim.x + threadIdx.x;
    if (i < n) out[i] = val;
}

// ---------------- probe: lora A/B order, ln g/b order, scales/biases dtype ----------------
__global__ void probe_kernel(const float* __restrict__ a1, const float* __restrict__ a2,
                             const float* __restrict__ g1, const float* __restrict__ g2,
                             const void* __restrict__ sc, const void* __restrict__ bi) {
    int lane = threadIdx.x;
    float s1 = 0.f, s2 = 0.f;
    for (int i = lane; i < 4096; i += 32) { s1 += fabsf(a1[i]); s2 += fabsf(a2[i]); }
#pragma unroll
    for (int o = 16; o; o >>= 1) {
        s1 += __shfl_xor_sync(0xffffffffu, s1, o);
        s2 += __shfl_xor_sync(0xffffffffu, s2, o);
    }
    float t1 = 0.f, t2 = 0.f;
    for (int i = lane; i < 1024; i += 32) { t1 += fabsf(g1[i]); t2 += fabsf(g2[i]); }
#pragma unroll
    for (int o = 16; o; o >>= 1) {
        t1 += __shfl_xor_sync(0xffffffffu, t1, o);
        t2 += __shfl_xor_sync(0xffffffffu, t2, o);
    }
    if (lane == 0) {
        g_flags[0] = (s1 < s2) ? 1 : 0;
        g_flags[1] = (t1 < t2) ? 1 : 0;
        {   // scales dtype: positive, ~(0.01, 0.06)
            const __half* h = (const __half*)sc;
            const __nv_bfloat16* b = (const __nv_bfloat16*)sc;
            const float* f = (const float*)sc;
            int c16 = 0, cbf = 0, c32 = 0;
            for (int i = 0; i < 256; i++) {
                float v = __half2float(h[i]);
                if (isfinite(v) && v > 0.004f && v < 0.3f) c16++;
                float vb = __bfloat162float(b[i]);
                if (isfinite(vb) && vb > 0.004f && vb < 0.3f) cbf++;
                float vf = f[i];
                if (isfinite(vf) && vf > 0.004f && vf < 0.3f) c32++;
            }
            int fl = 0, best = c16;
            if (cbf > best) { fl = 1; best = cbf; }
            if (c32 > best) { fl = 2; }
            g_flags[2] = fl;
        }
        {   // biases dtype: ~N(0, 0.01)
            const __half* h = (const __half*)bi;
            const __nv_bfloat16* b = (const __nv_bfloat16*)bi;
            const float* f = (const float*)bi;
            int c16 = 0, cbf = 0, c32 = 0;
            for (int i = 0; i < 256; i++) {
                float v = __half2float(h[i]);
                if (isfinite(v) && fabsf(v) < 0.5f) c16++;
                float vb = __bfloat162float(b[i]);
                if (isfinite(vb) && fabsf(vb) < 0.5f) cbf++;
                float vf = f[i];
                if (isfinite(vf) && fabsf(vf) < 0.5f) c32++;
            }
            int fl = 0, best = c16;
            if (cbf > best) { fl = 1; best = cbf; }
            if (c32 > best) { fl = 2; }
            g_flags[3] = fl;
        }
    }
}

// ---------------- lora t = X @ A^T, f32 SIMT ----------------
__global__ __launch_bounds__(256) void lora_t_kernel(const float* x, int xsel, int nX,
                                                     const float* out,
                                                     const float* __restrict__ Ac1,
                                                     const float* __restrict__ Ac2, int nA,
                                                     int li) {
    int lc = (li > NLIN - 1) ? (NLIN - 1) : li;   // JAX out-of-bounds index CLAMP semantics
    const float* Abase = g_flags[0] ? Ac2 : Ac1;
    size_t aoff = (size_t)lc * RANK * D;
    __shared__ float sx[8 * 128];
    __shared__ float sa[RANK * 129];
    int tid = threadIdx.x;
    int mi = tid >> 5;
    int ri = tid & 31;
    int m0 = blockIdx.x * 8;

    float acc = 0.f;
    for (int kc = 0; kc < D; kc += 128) {
#pragma unroll
        for (int i = 0; i < 4; i++) {
            int idx = tid + i * 256;
            int kk = idx & 127, mm = idx >> 7;
            sx[mm * 128 + kk] = xfetch(xsel, x, (size_t)nX, out,
                                       (size_t)(m0 + mm) * D + kc + kk);
        }
#pragma unroll
        for (int i = 0; i < 16; i++) {
            int idx = tid + i * 256;
            int kk = idx & 127, rr = idx >> 7;
            sa[rr * 129 + kk] = gld(Abase, aoff + (size_t)rr * D + kc + kk, (size_t)nA);
        }
        __syncthreads();
#pragma unroll 4
        for (int kk = 0; kk < 128; kk++)
            acc += sx[mi * 128 + kk] * sa[ri * 129 + kk];
        __syncthreads();
    }
    g_t[(size_t)(m0 + mi) * RANK + ri] = acc;
}

// ---------------- fused QLoRA linear: on-the-fly 4-bit dequant, SIMT fp32 ----------------
// Y = f32( f16( f16(X) @ W^T ) + bias ) + 0.125*(t @ Bl^T)  [+resid] [relu]
template <bool RELU, bool RESID>
__global__ __launch_bounds__(256) void gemm_kernel(
    const float* x, int xsel, int nX,
    float* out, long long nOut, int ysel,
    const int* __restrict__ q, long long nq,
    const void* __restrict__ sc, int ns,
    const void* __restrict__ biases, int nbias, int li,
    const float* __restrict__ Bc1, const float* __restrict__ Bc2, int nB,
    int rsel) {
    int lc = (li > NLIN - 1) ? (NLIN - 1) : li;   // JAX out-of-bounds index CLAMP semantics
    const float* Blbase = g_flags[0] ? Bc1 : Bc2;
    size_t bloff = (size_t)lc * D * RANK;

    __shared__ alignas(16) float pool[6336];
    float* sX = pool;           // [GBK][SX_STRIDE]
    float* sW = pool + 2112;    // [GBK][SW_STRIDE]

    int tid = threadIdx.x;
    int tx = tid & 15;
    int ty = tid >> 4;
    int m0 = blockIdx.y * GBM, n0 = blockIdx.x * GBN;
    int scfl = g_flags[2];

    const __half c215 = __float2half(2.0f / 15.0f);
    const __half hone = __float2half(1.0f);

    float acc[8][4];
#pragma unroll
    for (int i = 0; i < 8; i++)
#pragma unroll
        for (int j = 0; j < 4; j++) acc[i][j] = 0.f;

    for (int kt = 0; kt < D / GBK; ++kt) {
        int k0 = kt * GBK;
        // X tile 128m x 16k, rounded to f16 values (idempotent for f16 sources)
#pragma unroll
        for (int i = 0; i < 8; i++) {
            int idx = tid + i * 256;
            int kk = idx & 15, mm = idx >> 4;
            float v = xfetch(xsel, x, (size_t)nX, out, (size_t)(m0 + mm) * D + k0 + kk);
            sX[kk * SX_STRIDE + mm] = __half2float(__float2half(v));
        }
        // W tile 64n x 16k: fused exact-f16 dequant from q + scales
#pragma unroll
        for (int i = 0; i < 4; i++) {
            int idx = tid + i * 256;
            int kk = idx & 15, nn = idx >> 4;
            int row = n0 + nn, col = k0 + kk;
            size_t qi = (size_t)lc * D * D + (size_t)row * D + col;
            int qv = (qi < (size_t)nq) ? q[qi] : 0;
            __half scv = fetch_h(sc, (size_t)lc * D * (D / 16) + (size_t)row * (D / 16)
                                     + (col >> 4), (size_t)ns, scfl);
            __half w = __hmul(__hsub(__hmul(__int2half_rn(qv), c215), hone), scv);
            sW[kk * SW_STRIDE + nn] = __half2float(w);
        }
        __syncthreads();
#pragma unroll
        for (int k = 0; k < GBK; k++) {
            float4 rx0 = *(const float4*)&sX[k * SX_STRIDE + ty * 8];
            float4 rx1 = *(const float4*)&sX[k * SX_STRIDE + ty * 8 + 4];
            float4 rw  = *(const float4*)&sW[k * SW_STRIDE + tx * 4];
            float xm[8] = {rx0.x, rx0.y, rx0.z, rx0.w, rx1.x, rx1.y, rx1.z, rx1.w};
            float wn[4] = {rw.x, rw.y, rw.z, rw.w};
#pragma unroll
            for (int i = 0; i < 8; i++)
#pragma unroll
                for (int j = 0; j < 4; j++) acc[i][j] += xm[i] * wn[j];
        }
        __syncthreads();
    }

    // f16-round + f16 bias (reference numerics), widen to f32
    {
        int fl = g_flags[3];
        __half hb[4];
#pragma unroll
        for (int j = 0; j < 4; j++)
            hb[j] = fetch_h(biases, (size_t)lc * D + n0 + tx * 4 + j, (size_t)nbias, fl);
#pragma unroll
        for (int i = 0; i < 8; i++)
#pragma unroll
            for (int j = 0; j < 4; j++)
                acc[i][j] = __half2float(__hadd(__float2half(acc[i][j]), hb[j]));
    }

    // LoRA: smem-staged t (128x32) and 0.125*Bl (64x32), f32
    {
        float* tpool = pool;           // 128*33 = 4224
        float* bpool = pool + 4224;    // 64*33  = 2112
#pragma unroll
        for (int i = 0; i < 16; i++) {
            int idx = tid + i * 256;
            int rr = idx & 31, mm = idx >> 5;
            tpool[mm * 33 + rr] = g_t[(size_t)(m0 + mm) * RANK + rr];
        }
#pragma unroll
        for (int i = 0; i < 8; i++) {
            int idx = tid + i * 256;
            int rr = idx & 31, nn = idx >> 5;
            bpool[nn * 33 + rr] =
                0.125f * gld(Blbase, bloff + (size_t)(n0 + nn) * RANK + rr, (size_t)nB);
        }
        __syncthreads();
#pragma unroll 4
        for (int r = 0; r < RANK; r++) {
            float tv[8], bv[4];
#pragma unroll
            for (int i = 0; i < 8; i++) tv[i] = tpool[(ty * 8 + i) * 33 + r];
#pragma unroll
            for (int j = 0; j < 4; j++) bv[j] = bpool[(tx * 4 + j) * 33 + r];
#pragma unroll
            for (int i = 0; i < 8; i++)
#pragma unroll
                for (int j = 0; j < 4; j++) acc[i][j] += tv[i] * bv[j];
        }
    }

    // epilogue: residual / relu / store to f16 buffer or f32 d_out
#pragma unroll
    for (int i = 0; i < 8; i++) {
        int m = m0 + ty * 8 + i;
#pragma unroll
        for (int j = 0; j < 4; j++) {
            int c = n0 + tx * 4 + j;
            size_t gi = (size_t)m * D + c;
            float v = acc[i][j];
            if (RESID) v += (rsel == 0) ? out[gi] : gld(x, gi, (size_t)nX);
            if (RELU)  v = fmaxf(v, 0.f);
            if (ysel == 1)      g_r1h[gi] = __float2half(v);
            else if (ysel == 2) g_r2h[gi] = __float2half(v);
            else if ((long long)gi < nOut) out[gi] = v;
        }
    }
}

// ---------------- layernorm: warp per row, in-place on the d_out stream ----------------
__global__ __launch_bounds__(256) void ln_kernel(float* out, long long nOut,
                                                 const float* __restrict__ gc1,
                                                 const float* __restrict__ gc2, int ng,
                                                 int blk) {
    const float* gbase = g_flags[1] ? gc2 : gc1;
    const float* bbase = g_flags[1] ? gc1 : gc2;
    int row = blockIdx.x * 8 + (threadIdx.x >> 5);
    int lane = threadIdx.x & 31;
    float v[32];
    float s = 0.f;
#pragma unroll
    for (int i = 0; i < 32; i++) {
        size_t gi = (size_t)row * D + lane + i * 32;
        v[i] = ((long long)gi < nOut) ? out[gi] : 0.f;
        s += v[i];
    }
#pragma unroll
    for (int off = 16; off > 0; off >>= 1) s += __shfl_xor_sync(0xffffffffu, s, off);
    float mu = s * (1.f / D);
    float ss = 0.f;
#pragma unroll
    for (int i = 0; i < 32; i++) { float d = v[i] - mu; ss += d * d; }
#pragma unroll
    for (int off = 16; off > 0; off >>= 1) ss += __shfl_xor_sync(0xffffffffu, ss, off);
    float inv = rsqrtf(ss * (1.f / D) + 1e-5f);
#pragma unroll
    for (int i = 0; i < 32; i++) {
        int c = lane + i * 32;
        size_t pi = (size_t)blk * D + c;
        float gg = gld(gbase, pi, (size_t)ng);
        float bb = gld(bbase, pi, (size_t)ng);
        size_t gi = (size_t)row * D + c;
        if ((long long)gi < nOut) out[gi] = (v[i] - mu) * inv * gg + bb;
    }
}

// ---------------- host launch ----------------
extern "C" void kernel_launch(void* const* d_in, const int* in_sizes, int n_in,
                              void* d_out, int out_size) {
    float* out = (float*)d_out;

    int ix = -1, iq = -1, is_ = -1, ib = -1, iA = -1, iB = -1, ig = -1, ib2 = -1;
    for (int i = 0; i < n_in; i++) {
        int sz = in_sizes[i];
        if      (sz == 8388608)  { if (ix < 0) ix = i; }
        else if (sz == 15728640) { if (iq < 0) iq = i; }
        else if (sz == 983040)   { if (is_ < 0) is_ = i; }
        else if (sz == 15360)    { if (ib < 0) ib = i; }
        else if (sz == 491520)   { if (iA < 0) iA = i; else if (iB < 0) iB = i; }
        else if (sz == 5120)     { if (ig < 0) ig = i; else if (ib2 < 0) ib2 = i; }
    }
    bool ok = (n_in >= 8) && ix >= 0 && iq >= 0 && is_ >= 0 && ib >= 0 &&
              iA >= 0 && iB >= 0 && ig >= 0 && ib2 >= 0;
    if (!ok) {
        int mask = (ix >= 0 ? 1 : 0) | (iq >= 0 ? 2 : 0) | (is_ >= 0 ? 4 : 0) |
                   (ib >= 0 ? 8 : 0) | ((iA >= 0 && iB >= 0) ? 16 : 0) |
                   ((ig >= 0 && ib2 >= 0) ? 32 : 0);
        float val = 1.0e6f * (float)n_in + 1000.0f * (float)mask;
        long long n = out_size;
        if (n > 8388608LL) n = 8388608LL;
        diag_kernel<<<(int)((n + 255) / 256), 256>>>(out, n, val);
        return;
    }

    const float* x      = (const float*)d_in[ix];
    const int*   qw     = (const int*)d_in[iq];
    const void*  scales = d_in[is_];
    const void*  biases = d_in[ib];
    const float* lA1    = (const float*)d_in[iA];
    const float* lA2    = (const float*)d_in[iB];
    const float* lg1    = (const float*)d_in[ig];
    const float* lg2    = (const float*)d_in[ib2];
    int nx = in_sizes[ix], ns = in_sizes[is_], nb = in_sizes[ib];
    int nA = in_sizes[iA], nB = in_sizes[iB], ng = in_sizes[ig];
    long long nq = in_sizes[iq];
    long long nOut = out_size;

    probe_kernel<<<1, 32>>>(lA1, lA2, lg1, lg2, scales, biases);

    dim3 ggrid(D / GBN, MROWS / GBM);   // (16, 64)
    const int ltg = MROWS / 8;

    int li = 0;
    for (int blk = 0; blk < 6; blk++) {
        int hsel = (blk == 0) ? -1 : 0;   // residual stream: ext x first, then d_out
        // linear 0 (+relu): h -> r1h (f16)
        lora_t_kernel<<<ltg, 256>>>(x, hsel, nx, out, lA1, lA2, nA, li);
        gemm_kernel<true, false><<<ggrid, 256>>>(x, hsel, nx, out, nOut, 1,
                                                 qw, nq, scales, ns, biases, nb, li,
                                                 lA1, lA2, nB, 0);
        li++;
        // linear 1 (+relu): r1h -> r2h (f16)
        lora_t_kernel<<<ltg, 256>>>(x, 1, nx, out, lA1, lA2, nA, li);
        gemm_kernel<true, false><<<ggrid, 256>>>(x, 1, nx, out, nOut, 2,
                                                 qw, nq, scales, ns, biases, nb, li,
                                                 lA1, lA2, nB, 0);
        li++;
        // linear 2 (+block residual): r2h -> d_out (in-place elementwise resid add)
        lora_t_kernel<<<ltg, 256>>>(x, 2, nx, out, lA1, lA2, nA, li);
        gemm_kernel<false, true><<<ggrid, 256>>>(x, 2, nx, out, nOut, 0,
                                                 qw, nq, scales, ns, biases, nb, li,
                                                 lA1, lA2, nB, hsel);
        li++;
        if (blk < 5) {
            ln_kernel<<<MROWS / 8, 256>>>(out, nOut, lg1, lg2, ng, blk);
        }
    }
}

// round 11
// speedup vs baseline: 2.4904x; 2.4904x over previous
#include <cuda_runtime.h>
#include <cuda_fp16.h>
#include <cuda_bf16.h>
#include <cstdint>

#define D 1024
#define NLIN 15
#define MROWS 8192
#define RANK 32
#define BM 128
#define BN 128
#define BK 32
#define SSTR 40   // smem row stride in halves (80B) -> conflict-free fragment LDS

// ---------------- device scratch: 33MB total ----------------
__device__ __half g_r1h[MROWS * D];   // relu(lin0) f16 (exact for main path)
__device__ __half g_r2h[MROWS * D];   // relu(lin1) f16
__device__ float  g_t[MROWS * RANK];  // lora t = x @ A^T
__device__ int    g_flags[4];         // 0: lora swap, 1: ln swap, 2/3: scales/biases dtype

__device__ __forceinline__ float gld(const float* p, size_t i, size_t n) {
    return (i < n) ? p[i] : 0.f;
}
__device__ __forceinline__ __half fetch_h(const void* p, size_t i, size_t n, int fl) {
    if (i >= n) return __float2half(0.f);
    if (fl == 2) return __float2half(((const float*)p)[i]);
    if (fl == 1) return __float2half(__bfloat162float(((const __nv_bfloat16*)p)[i]));
    return ((const __half*)p)[i];
}
// activation fetch: sel -1 = external x (guarded), 0 = d_out stream, 1/2 = f16 buffers
__device__ __forceinline__ float xfetch(int sel, const float* x, size_t nX,
                                        const float* out, size_t gi) {
    switch (sel) {
        case 1:  return __half2float(g_r1h[gi]);
        case 2:  return __half2float(g_r2h[gi]);
        case 0:  return out[gi];
        default: return (gi < nX) ? x[gi] : 0.f;
    }
}

// ---------------- mma.sync m16n8k16 f16*f16 -> f32 ----------------
__device__ __forceinline__ void mma16816(float* d, const uint32_t* a, const uint32_t* b) {
    asm volatile(
        "mma.sync.aligned.m16n8k16.row.col.f32.f16.f16.f32 "
        "{%0,%1,%2,%3}, {%4,%5,%6,%7}, {%8,%9}, {%0,%1,%2,%3};\n"
        : "+f"(d[0]), "+f"(d[1]), "+f"(d[2]), "+f"(d[3])
        : "r"(a[0]), "r"(a[1]), "r"(a[2]), "r"(a[3]), "r"(b[0]), "r"(b[1]));
}

// ---------------- diagnostic fill ----------------
__global__ void diag_kernel(float* out, long long n, float val) {
    long long i = (long long)blockIdx.x * blockDim.x + threadIdx.x;
    if (i < n) out[i] = val;
}

// ---------------- probe: lora A/B order, ln g/b order, scales/biases dtype ----------------
__global__ void probe_kernel(const float* __restrict__ a1, const float* __restrict__ a2,
                             const float* __restrict__ g1, const float* __restrict__ g2,
                             const void* __restrict__ sc, const void* __restrict__ bi) {
    int lane = threadIdx.x;
    float s1 = 0.f, s2 = 0.f;
    for (int i = lane; i < 4096; i += 32) { s1 += fabsf(a1[i]); s2 += fabsf(a2[i]); }
#pragma unroll
    for (int o = 16; o; o >>= 1) {
        s1 += __shfl_xor_sync(0xffffffffu, s1, o);
        s2 += __shfl_xor_sync(0xffffffffu, s2, o);
    }
    float t1 = 0.f, t2 = 0.f;
    for (int i = lane; i < 1024; i += 32) { t1 += fabsf(g1[i]); t2 += fabsf(g2[i]); }
#pragma unroll
    for (int o = 16; o; o >>= 1) {
        t1 += __shfl_xor_sync(0xffffffffu, t1, o);
        t2 += __shfl_xor_sync(0xffffffffu, t2, o);
    }
    if (lane == 0) {
        g_flags[0] = (s1 < s2) ? 1 : 0;
        g_flags[1] = (t1 < t2) ? 1 : 0;
        {
            const __half* h = (const __half*)sc;
            const __nv_bfloat16* b = (const __nv_bfloat16*)sc;
            const float* f = (const float*)sc;
            int c16 = 0, cbf = 0, c32 = 0;
            for (int i = 0; i < 256; i++) {
                float v = __half2float(h[i]);
                if (isfinite(v) && v > 0.004f && v < 0.3f) c16++;
                float vb = __bfloat162float(b[i]);
                if (isfinite(vb) && vb > 0.004f && vb < 0.3f) cbf++;
                float vf = f[i];
                if (isfinite(vf) && vf > 0.004f && vf < 0.3f) c32++;
            }
            int fl = 0, best = c16;
            if (cbf > best) { fl = 1; best = cbf; }
            if (c32 > best) { fl = 2; }
            g_flags[2] = fl;
        }
        {
            const __half* h = (const __half*)bi;
            const __nv_bfloat16* b = (const __nv_bfloat16*)bi;
            const float* f = (const float*)bi;
            int c16 = 0, cbf = 0, c32 = 0;
            for (int i = 0; i < 256; i++) {
                float v = __half2float(h[i]);
                if (isfinite(v) && fabsf(v) < 0.5f) c16++;
                float vb = __bfloat162float(b[i]);
                if (isfinite(vb) && fabsf(vb) < 0.5f) cbf++;
                float vf = f[i];
                if (isfinite(vf) && fabsf(vf) < 0.5f) c32++;
            }
            int fl = 0, best = c16;
            if (cbf > best) { fl = 1; best = cbf; }
            if (c32 > best) { fl = 2; }
            g_flags[3] = fl;
        }
    }
}

// ---------------- lora t = X @ A^T via MMA (f16 in, f32 accum) ----------------
// 64 blocks x 256 threads; 8 warps, each one m16 tile; N=RANK=32 (4 n8 frags).
__global__ __launch_bounds__(256) void lora_t_kernel(const float* x, int xsel, int nX,
                                                     const float* out,
                                                     const float* __restrict__ Ac1,
                                                     const float* __restrict__ Ac2, int nA,
                                                     int li) {
    int lc = (li > NLIN - 1) ? (NLIN - 1) : li;   // JAX clamp semantics
    const float* Abase = g_flags[0] ? Ac2 : Ac1;
    size_t aoff = (size_t)lc * RANK * D;
    __shared__ __half sA[BM][SSTR];
    __shared__ __half sW[RANK][SSTR];
    int tid = threadIdx.x;
    int wid = tid >> 5, lane = tid & 31;
    int gid = lane >> 2, tig = lane & 3;
    int m0 = blockIdx.x * BM;

    float acc[4][4];
#pragma unroll
    for (int ni = 0; ni < 4; ni++)
#pragma unroll
        for (int j = 0; j < 4; j++) acc[ni][j] = 0.f;

    for (int kt = 0; kt < D / BK; ++kt) {
        int k0 = kt * BK;
#pragma unroll
        for (int i = 0; i < 16; i++) {             // X tile 128x32
            int e = tid + i * 256;
            int r = e >> 5, c = e & 31;
            sA[r][c] = __float2half(xfetch(xsel, x, (size_t)nX, out,
                                           (size_t)(m0 + r) * D + k0 + c));
        }
#pragma unroll
        for (int i = 0; i < 4; i++) {              // A tile 32x32 (in-bounds: lc<=14)
            int e = tid + i * 256;
            int r = e >> 5, c = e & 31;
            sW[r][c] = __float2half(Abase[aoff + (size_t)r * D + k0 + c]);
        }
        __syncthreads();
#pragma unroll
        for (int kk = 0; kk < 2; kk++) {
            int kb = kk * 16;
            uint32_t af[4];
            int rb = wid * 16;
            af[0] = *(const uint32_t*)&sA[rb + gid][kb + tig * 2];
            af[1] = *(const uint32_t*)&sA[rb + gid + 8][kb + tig * 2];
            af[2] = *(const uint32_t*)&sA[rb + gid][kb + tig * 2 + 8];
            af[3] = *(const uint32_t*)&sA[rb + gid + 8][kb + tig * 2 + 8];
#pragma unroll
            for (int ni = 0; ni < 4; ni++) {
                uint32_t bf[2];
                bf[0] = *(const uint32_t*)&sW[ni * 8 + gid][kb + tig * 2];
                bf[1] = *(const uint32_t*)&sW[ni * 8 + gid][kb + tig * 2 + 8];
                mma16816(acc[ni], af, bf);
            }
        }
        __syncthreads();
    }
#pragma unroll
    for (int ni = 0; ni < 4; ni++) {
        int r0 = m0 + wid * 16 + gid;
        int c0 = ni * 8 + tig * 2;
        g_t[(size_t)r0 * RANK + c0]           = acc[ni][0];
        g_t[(size_t)r0 * RANK + c0 + 1]       = acc[ni][1];
        g_t[(size_t)(r0 + 8) * RANK + c0]     = acc[ni][2];
        g_t[(size_t)(r0 + 8) * RANK + c0 + 1] = acc[ni][3];
    }
}

// ---------------- fused QLoRA linear via MMA, on-the-fly 4-bit dequant ----------------
// Y = f32( f16( f16(X) @ W^T ) + bias ) + 0.125*(t @ Bl^T)  [+resid] [relu]
// 256 threads, 8 warps as 4(m) x 2(n); warp tile 32x64 = 2 m16 x 8 n8.
template <bool RELU, bool RESID>
__global__ __launch_bounds__(256) void gemm_kernel(
    const float* x, int xsel, int nX,
    float* out, long long nOut, int ysel,
    const int* __restrict__ q,
    const void* __restrict__ sc, int ns,
    const void* __restrict__ biases, int nbias, int li,
    const float* __restrict__ Bc1, const float* __restrict__ Bc2, int nB,
    int rsel) {
    int lc = (li > NLIN - 1) ? (NLIN - 1) : li;   // JAX clamp semantics
    const float* Blbase = g_flags[0] ? Bc1 : Bc2;
    size_t bloff = (size_t)lc * D * RANK;

    __shared__ __half sA[BM][SSTR];
    __shared__ __half sB[BN][SSTR];

    int tid = threadIdx.x;
    int wid = tid >> 5, lane = tid & 31;
    int gid = lane >> 2, tig = lane & 3;
    int wm = wid & 3, wn = wid >> 2;
    int m0 = blockIdx.y * BM, n0 = blockIdx.x * BN;
    int scfl = g_flags[2];

    const __half c215 = __float2half(2.0f / 15.0f);
    const __half hone = __float2half(1.0f);

    float acc[2][8][4];
#pragma unroll
    for (int mi = 0; mi < 2; mi++)
#pragma unroll
        for (int ni = 0; ni < 8; ni++)
#pragma unroll
            for (int j = 0; j < 4; j++) acc[mi][ni][j] = 0.f;

    // thread's dequant assignment: one 16-col scale group of one row per thread
    int dq_row = tid >> 1;          // 0..127
    int dq_g   = tid & 1;           // 0/1 (col group of 16)

    for (int kt = 0; kt < D / BK; ++kt) {
        int k0 = kt * BK;
        // A tile 128x32: scalar loads, f16-round (idempotent for f16 sources)
#pragma unroll
        for (int i = 0; i < 16; i++) {
            int e = tid + i * 256;
            int r = e >> 5, c = e & 31;
            sA[r][c] = __float2half(xfetch(xsel, x, (size_t)nX, out,
                                           (size_t)(m0 + r) * D + k0 + c));
        }
        // B tile 128x32: fused exact-f16 dequant. int4 q loads (64B-aligned, in-bounds).
        {
            int row = n0 + dq_row;
            int colb = k0 + dq_g * 16;
            const int4* qp = (const int4*)(q + (size_t)lc * D * D + (size_t)row * D + colb);
            __half scv = fetch_h(sc, (size_t)lc * D * (D / 16) + (size_t)row * (D / 16)
                                     + (colb >> 4), (size_t)ns, scfl);
#pragma unroll
            for (int v4 = 0; v4 < 4; v4++) {
                int4 qv = qp[v4];
                __half w0 = __hmul(__hsub(__hmul(__int2half_rn(qv.x), c215), hone), scv);
                __half w1 = __hmul(__hsub(__hmul(__int2half_rn(qv.y), c215), hone), scv);
                __half w2 = __hmul(__hsub(__hmul(__int2half_rn(qv.z), c215), hone), scv);
                __half w3 = __hmul(__hsub(__hmul(__int2half_rn(qv.w), c215), hone), scv);
                int cb = dq_g * 16 + v4 * 4;
                *(__half2*)&sB[dq_row][cb]     = __halves2half2(w0, w1);
                *(__half2*)&sB[dq_row][cb + 2] = __halves2half2(w2, w3);
            }
        }
        __syncthreads();
#pragma unroll
        for (int kk = 0; kk < 2; kk++) {
            int kb = kk * 16;
            uint32_t af[2][4], bf[8][2];
#pragma unroll
            for (int mi = 0; mi < 2; mi++) {
                int rb = wm * 32 + mi * 16;
                af[mi][0] = *(const uint32_t*)&sA[rb + gid][kb + tig * 2];
                af[mi][1] = *(const uint32_t*)&sA[rb + gid + 8][kb + tig * 2];
                af[mi][2] = *(const uint32_t*)&sA[rb + gid][kb + tig * 2 + 8];
                af[mi][3] = *(const uint32_t*)&sA[rb + gid + 8][kb + tig * 2 + 8];
            }
#pragma unroll
            for (int ni = 0; ni < 8; ni++) {
                int nb = wn * 64 + ni * 8 + gid;
                bf[ni][0] = *(const uint32_t*)&sB[nb][kb + tig * 2];
                bf[ni][1] = *(const uint32_t*)&sB[nb][kb + tig * 2 + 8];
            }
#pragma unroll
            for (int mi = 0; mi < 2; mi++)
#pragma unroll
                for (int ni = 0; ni < 8; ni++) mma16816(acc[mi][ni], af[mi], bf[ni]);
        }
        __syncthreads();
    }

    // f16-round + f16 bias (reference numerics), widen to f32
    {
        int fl = g_flags[3];
#pragma unroll
        for (int ni = 0; ni < 8; ni++) {
            int c0 = n0 + wn * 64 + ni * 8 + tig * 2;
            __half b0 = fetch_h(biases, (size_t)lc * D + c0, (size_t)nbias, fl);
            __half b1 = fetch_h(biases, (size_t)lc * D + c0 + 1, (size_t)nbias, fl);
#pragma unroll
            for (int mi = 0; mi < 2; mi++) {
                acc[mi][ni][0] = __half2float(__hadd(__float2half(acc[mi][ni][0]), b0));
                acc[mi][ni][1] = __half2float(__hadd(__float2half(acc[mi][ni][1]), b1));
                acc[mi][ni][2] = __half2float(__hadd(__float2half(acc[mi][ni][2]), b0));
                acc[mi][ni][3] = __half2float(__hadd(__float2half(acc[mi][ni][3]), b1));
            }
        }
    }

    // LoRA as 2 extra MMA k-steps: sA <- t tile (f16), sB <- 0.125*Bl (f16)
#pragma unroll
    for (int i = 0; i < 16; i++) {
        int e = tid + i * 256;
        int r = e >> 5, c = e & 31;
        sA[r][c] = __float2half(g_t[(size_t)(m0 + r) * RANK + c]);
        sB[r][c] = __float2half(0.125f * gld(Blbase, bloff + (size_t)(n0 + r) * RANK + c,
                                             (size_t)nB));
    }
    __syncthreads();
#pragma unroll
    for (int kk = 0; kk < 2; kk++) {
        int kb = kk * 16;
        uint32_t af[2][4], bf[8][2];
#pragma unroll
        for (int mi = 0; mi < 2; mi++) {
            int rb = wm * 32 + mi * 16;
            af[mi][0] = *(const uint32_t*)&sA[rb + gid][kb + tig * 2];
            af[mi][1] = *(const uint32_t*)&sA[rb + gid + 8][kb + tig * 2];
            af[mi][2] = *(const uint32_t*)&sA[rb + gid][kb + tig * 2 + 8];
            af[mi][3] = *(const uint32_t*)&sA[rb + gid + 8][kb + tig * 2 + 8];
        }
#pragma unroll
        for (int ni = 0; ni < 8; ni++) {
            int nb = wn * 64 + ni * 8 + gid;
            bf[ni][0] = *(const uint32_t*)&sB[nb][kb + tig * 2];
            bf[ni][1] = *(const uint32_t*)&sB[nb][kb + tig * 2 + 8];
        }
#pragma unroll
        for (int mi = 0; mi < 2; mi++)
#pragma unroll
            for (int ni = 0; ni < 8; ni++) mma16816(acc[mi][ni], af[mi], bf[ni]);
    }

    // epilogue: residual / relu / store (f16 buffers or f32 d_out)
#pragma unroll
    for (int mi = 0; mi < 2; mi++)
#pragma unroll
        for (int ni = 0; ni < 8; ni++) {
            int r0 = m0 + wm * 32 + mi * 16 + gid;
            int c0 = n0 + wn * 64 + ni * 8 + tig * 2;
#pragma unroll
            for (int h = 0; h < 2; h++) {        // h=0: row r0, h=1: row r0+8
                int m = r0 + h * 8;
                float v0 = acc[mi][ni][h * 2], v1 = acc[mi][ni][h * 2 + 1];
                size_t gi = (size_t)m * D + c0;
                if (RESID) {
                    if (rsel == 0) { v0 += out[gi]; v1 += out[gi + 1]; }
                    else { v0 += gld(x, gi, (size_t)nX); v1 += gld(x, gi + 1, (size_t)nX); }
                }
                if (RELU) { v0 = fmaxf(v0, 0.f); v1 = fmaxf(v1, 0.f); }
                if (ysel == 1) {
                    g_r1h[gi] = __float2half(v0); g_r1h[gi + 1] = __float2half(v1);
                } else if (ysel == 2) {
                    g_r2h[gi] = __float2half(v0); g_r2h[gi + 1] = __float2half(v1);
                } else if ((long long)gi + 1 < nOut) {
                    out[gi] = v0; out[gi + 1] = v1;
                }
            }
        }
}

// ---------------- layernorm: warp per row, in-place on the d_out stream ----------------
__global__ __launch_bounds__(256) void ln_kernel(float* out, long long nOut,
                                                 const float* __restrict__ gc1,
                                                 const float* __restrict__ gc2, int ng,
                                                 int blk) {
    const float* gbase = g_flags[1] ? gc2 : gc1;
    const float* bbase = g_flags[1] ? gc1 : gc2;
    int row = blockIdx.x * 8 + (threadIdx.x >> 5);
    int lane = threadIdx.x & 31;
    float v[32];
    float s = 0.f;
#pragma unroll
    for (int i = 0; i < 32; i++) {
        size_t gi = (size_t)row * D + lane + i * 32;
        v[i] = ((long long)gi < nOut) ? out[gi] : 0.f;
        s += v[i];
    }
#pragma unroll
    for (int off = 16; off > 0; off >>= 1) s += __shfl_xor_sync(0xffffffffu, s, off);
    float mu = s * (1.f / D);
    float ss = 0.f;
#pragma unroll
    for (int i = 0; i < 32; i++) { float d = v[i] - mu; ss += d * d; }
#pragma unroll
    for (int off = 16; off > 0; off >>= 1) ss += __shfl_xor_sync(0xffffffffu, ss, off);
    float inv = rsqrtf(ss * (1.f / D) + 1e-5f);
#pragma unroll
    for (int i = 0; i < 32; i++) {
        int c = lane + i * 32;
        size_t pi = (size_t)blk * D + c;
        float gg = gld(gbase, pi, (size_t)ng);
        float bb = gld(bbase, pi, (size_t)ng);
        size_t gi = (size_t)row * D + c;
        if ((long long)gi < nOut) out[gi] = (v[i] - mu) * inv * gg + bb;
    }
}

// ---------------- host launch ----------------
extern "C" void kernel_launch(void* const* d_in, const int* in_sizes, int n_in,
                              void* d_out, int out_size) {
    float* out = (float*)d_out;

    int ix = -1, iq = -1, is_ = -1, ib = -1, iA = -1, iB = -1, ig = -1, ib2 = -1;
    for (int i = 0; i < n_in; i++) {
        int sz = in_sizes[i];
        if      (sz == 8388608)  { if (ix < 0) ix = i; }
        else if (sz == 15728640) { if (iq < 0) iq = i; }
        else if (sz == 983040)   { if (is_ < 0) is_ = i; }
        else if (sz == 15360)    { if (ib < 0) ib = i; }
        else if (sz == 491520)   { if (iA < 0) iA = i; else if (iB < 0) iB = i; }
        else if (sz == 5120)     { if (ig < 0) ig = i; else if (ib2 < 0) ib2 = i; }
    }
    bool ok = (n_in >= 8) && ix >= 0 && iq >= 0 && is_ >= 0 && ib >= 0 &&
              iA >= 0 && iB >= 0 && ig >= 0 && ib2 >= 0;
    if (!ok) {
        int mask = (ix >= 0 ? 1 : 0) | (iq >= 0 ? 2 : 0) | (is_ >= 0 ? 4 : 0) |
                   (ib >= 0 ? 8 : 0) | ((iA >= 0 && iB >= 0) ? 16 : 0) |
                   ((ig >= 0 && ib2 >= 0) ? 32 : 0);
        float val = 1.0e6f * (float)n_in + 1000.0f * (float)mask;
        long long n = out_size;
        if (n > 8388608LL) n = 8388608LL;
        diag_kernel<<<(int)((n + 255) / 256), 256>>>(out, n, val);
        return;
    }

    const float* x      = (const float*)d_in[ix];
    const int*   qw     = (const int*)d_in[iq];
    const void*  scales = d_in[is_];
    const void*  biases = d_in[ib];
    const float* lA1    = (const float*)d_in[iA];
    const float* lA2    = (const float*)d_in[iB];
    const float* lg1    = (const float*)d_in[ig];
    const float* lg2    = (const float*)d_in[ib2];
    int nx = in_sizes[ix], ns = in_sizes[is_], nb = in_sizes[ib];
    int nA = in_sizes[iA], nB = in_sizes[iB], ng = in_sizes[ig];
    long long nOut = out_size;

    probe_kernel<<<1, 32>>>(lA1, lA2, lg1, lg2, scales, biases);

    dim3 ggrid(D / BN, MROWS / BM);   // (8, 64)
    const int ltg = MROWS / BM;        // 64

    int li = 0;
    for (int blk = 0; blk < 6; blk++) {
        int hsel = (blk == 0) ? -1 : 0;   // residual stream: ext x first, then d_out
        // linear 0 (+relu): h -> r1h (f16)
        lora_t_kernel<<<ltg, 256>>>(x, hsel, nx, out, lA1, lA2, nA, li);
        gemm_kernel<true, false><<<ggrid, 256>>>(x, hsel, nx, out, nOut, 1,
                                                 qw, scales, ns, biases, nb, li,
                                                 lA1, lA2, nB, 0);
        li++;
        // linear 1 (+relu): r1h -> r2h (f16)
        lora_t_kernel<<<ltg, 256>>>(x, 1, nx, out, lA1, lA2, nA, li);
        gemm_kernel<true, false><<<ggrid, 256>>>(x, 1, nx, out, nOut, 2,
                                                 qw, scales, ns, biases, nb, li,
                                                 lA1, lA2, nB, 0);
        li++;
        // linear 2 (+block residual): r2h -> d_out (in-place resid add)
        lora_t_kernel<<<ltg, 256>>>(x, 2, nx, out, lA1, lA2, nA, li);
        gemm_kernel<false, true><<<ggrid, 256>>>(x, 2, nx, out, nOut, 0,
                                                 qw, scales, ns, biases, nb, li,
                                                 lA1, lA2, nB, hsel);
        li++;
        if (blk < 5) {
            ln_kernel<<<MROWS / 8, 256>>>(out, nOut, lg1, lg2, ng, blk);
        }
    }
}

// round 12
// speedup vs baseline: 4.3180x; 1.7339x over previous
#include <cuda_runtime.h>
#include <cuda_fp16.h>
#include <cuda_bf16.h>
#include <cstdint>

#define D 1024
#define NLIN 15
#define MROWS 8192
#define RANK 32
#define BM 128
#define BN 128
#define BK 32
#define NT (D / BK)   // 32 k-tiles
#define SSTR 40       // smem row stride in halves (80B): conflict-free frag LDS, 16B-aligned rows
#define KSPLIT 4

// ---------------- device scratch: 36MB total ----------------
__device__ __half g_r1h[MROWS * D];              // relu(lin0) f16 (exact for main path)
__device__ __half g_r2h[MROWS * D];              // relu(lin1) f16
__device__ float  g_tp[KSPLIT * MROWS * RANK];   // lora t partials (K-split)
__device__ int    g_flags[4];                    // 0: lora swap, 1: ln swap, 2/3: dtypes

__device__ __forceinline__ float gld(const float* p, size_t i, size_t n) {
    return (i < n) ? p[i] : 0.f;
}
__device__ __forceinline__ __half fetch_h(const void* p, size_t i, size_t n, int fl) {
    if (i >= n) return __float2half(0.f);
    if (fl == 2) return __float2half(((const float*)p)[i]);
    if (fl == 1) return __float2half(__bfloat162float(((const __nv_bfloat16*)p)[i]));
    return ((const __half*)p)[i];
}
__device__ __forceinline__ float xfetch(int sel, const float* x, size_t nX,
                                        const float* out, size_t gi) {
    switch (sel) {
        case 1:  return __half2float(g_r1h[gi]);
        case 2:  return __half2float(g_r2h[gi]);
        case 0:  return out[gi];
        default: return (gi < nX) ? x[gi] : 0.f;
    }
}

// ---------------- mma.sync m16n8k16 f16*f16 -> f32 ----------------
__device__ __forceinline__ void mma16816(float* d, const uint32_t* a, const uint32_t* b) {
    asm volatile(
        "mma.sync.aligned.m16n8k16.row.col.f32.f16.f16.f32 "
        "{%0,%1,%2,%3}, {%4,%5,%6,%7}, {%8,%9}, {%0,%1,%2,%3};\n"
        : "+f"(d[0]), "+f"(d[1]), "+f"(d[2]), "+f"(d[3])
        : "r"(a[0]), "r"(a[1]), "r"(a[2]), "r"(a[3]), "r"(b[0]), "r"(b[1]));
}

// ---------------- diagnostic fill ----------------
__global__ void diag_kernel(float* out, long long n, float val) {
    long long i = (long long)blockIdx.x * blockDim.x + threadIdx.x;
    if (i < n) out[i] = val;
}

// ---------------- probe (unchanged) ----------------
__global__ void probe_kernel(const float* __restrict__ a1, const float* __restrict__ a2,
                             const float* __restrict__ g1, const float* __restrict__ g2,
                             const void* __restrict__ sc, const void* __restrict__ bi) {
    int lane = threadIdx.x;
    float s1 = 0.f, s2 = 0.f;
    for (int i = lane; i < 4096; i += 32) { s1 += fabsf(a1[i]); s2 += fabsf(a2[i]); }
#pragma unroll
    for (int o = 16; o; o >>= 1) {
        s1 += __shfl_xor_sync(0xffffffffu, s1, o);
        s2 += __shfl_xor_sync(0xffffffffu, s2, o);
    }
    float t1 = 0.f, t2 = 0.f;
    for (int i = lane; i < 1024; i += 32) { t1 += fabsf(g1[i]); t2 += fabsf(g2[i]); }
#pragma unroll
    for (int o = 16; o; o >>= 1) {
        t1 += __shfl_xor_sync(0xffffffffu, t1, o);
        t2 += __shfl_xor_sync(0xffffffffu, t2, o);
    }
    if (lane == 0) {
        g_flags[0] = (s1 < s2) ? 1 : 0;
        g_flags[1] = (t1 < t2) ? 1 : 0;
        {
            const __half* h = (const __half*)sc;
            const __nv_bfloat16* b = (const __nv_bfloat16*)sc;
            const float* f = (const float*)sc;
            int c16 = 0, cbf = 0, c32 = 0;
            for (int i = 0; i < 256; i++) {
                float v = __half2float(h[i]);
                if (isfinite(v) && v > 0.004f && v < 0.3f) c16++;
                float vb = __bfloat162float(b[i]);
                if (isfinite(vb) && vb > 0.004f && vb < 0.3f) cbf++;
                float vf = f[i];
                if (isfinite(vf) && vf > 0.004f && vf < 0.3f) c32++;
            }
            int fl = 0, best = c16;
            if (cbf > best) { fl = 1; best = cbf; }
            if (c32 > best) { fl = 2; }
            g_flags[2] = fl;
        }
        {
            const __half* h = (const __half*)bi;
            const __nv_bfloat16* b = (const __nv_bfloat16*)bi;
            const float* f = (const float*)bi;
            int c16 = 0, cbf = 0, c32 = 0;
            for (int i = 0; i < 256; i++) {
                float v = __half2float(h[i]);
                if (isfinite(v) && fabsf(v) < 0.5f) c16++;
                float vb = __bfloat162float(b[i]);
                if (isfinite(vb) && fabsf(vb) < 0.5f) cbf++;
                float vf = f[i];
                if (isfinite(vf) && fabsf(vf) < 0.5f) c32++;
            }
            int fl = 0, best = c16;
            if (cbf > best) { fl = 1; best = cbf; }
            if (c32 > best) { fl = 2; }
            g_flags[3] = fl;
        }
    }
}

// ---------------- lora t partials: K-split 4, MMA ----------------
// grid (64, KSPLIT); each block: 128 rows x RANK over a 256-wide K chunk.
__global__ __launch_bounds__(256) void lora_t_kernel(const float* x, int xsel, int nX,
                                                     const float* out,
                                                     const float* __restrict__ Ac1,
                                                     const float* __restrict__ Ac2,
                                                     int li) {
    int lc = (li > NLIN - 1) ? (NLIN - 1) : li;   // JAX clamp semantics
    const float* Abase = g_flags[0] ? Ac2 : Ac1;
    size_t aoff = (size_t)lc * RANK * D;
    __shared__ __half sA[BM][SSTR];
    __shared__ __half sW[RANK][SSTR];
    int tid = threadIdx.x;
    int wid = tid >> 5, lane = tid & 31;
    int gid = lane >> 2, tig = lane & 3;
    int m0 = blockIdx.x * BM;
    int ks = blockIdx.y;

    float acc[4][4];
#pragma unroll
    for (int ni = 0; ni < 4; ni++)
#pragma unroll
        for (int j = 0; j < 4; j++) acc[ni][j] = 0.f;

    for (int kt = 0; kt < NT / KSPLIT; ++kt) {
        int k0 = ks * (D / KSPLIT) + kt * BK;
#pragma unroll
        for (int i = 0; i < 16; i++) {
            int e = tid + i * 256;
            int r = e >> 5, c = e & 31;
            sA[r][c] = __float2half(xfetch(xsel, x, (size_t)nX, out,
                                           (size_t)(m0 + r) * D + k0 + c));
        }
#pragma unroll
        for (int i = 0; i < 4; i++) {
            int e = tid + i * 256;
            int r = e >> 5, c = e & 31;
            sW[r][c] = __float2half(Abase[aoff + (size_t)r * D + k0 + c]);
        }
        __syncthreads();
#pragma unroll
        for (int kk = 0; kk < 2; kk++) {
            int kb = kk * 16;
            uint32_t af[4];
            int rb = wid * 16;
            af[0] = *(const uint32_t*)&sA[rb + gid][kb + tig * 2];
            af[1] = *(const uint32_t*)&sA[rb + gid + 8][kb + tig * 2];
            af[2] = *(const uint32_t*)&sA[rb + gid][kb + tig * 2 + 8];
            af[3] = *(const uint32_t*)&sA[rb + gid + 8][kb + tig * 2 + 8];
#pragma unroll
            for (int ni = 0; ni < 4; ni++) {
                uint32_t bf[2];
                bf[0] = *(const uint32_t*)&sW[ni * 8 + gid][kb + tig * 2];
                bf[1] = *(const uint32_t*)&sW[ni * 8 + gid][kb + tig * 2 + 8];
                mma16816(acc[ni], af, bf);
            }
        }
        __syncthreads();
    }
    float* tp = g_tp + (size_t)ks * MROWS * RANK;
#pragma unroll
    for (int ni = 0; ni < 4; ni++) {
        int r0 = m0 + wid * 16 + gid;
        int c0 = ni * 8 + tig * 2;
        tp[(size_t)r0 * RANK + c0]           = acc[ni][0];
        tp[(size_t)r0 * RANK + c0 + 1]       = acc[ni][1];
        tp[(size_t)(r0 + 8) * RANK + c0]     = acc[ni][2];
        tp[(size_t)(r0 + 8) * RANK + c0 + 1] = acc[ni][3];
    }
}

// ---------------- fused QLoRA linear: double-buffered, vector loads ----------------
// XK: 0 = f32 source via xf32 ptr; 1 = g_r1h; 2 = g_r2h.
template <int XK, bool RELU, bool RESID>
__global__ __launch_bounds__(256) void gemm_kernel(
    const float* __restrict__ xf32,
    float* __restrict__ out, long long nOut, int ysel,
    const int* __restrict__ q,
    const void* __restrict__ sc, int ns,
    const void* __restrict__ biases, int nbias, int li,
    const float* __restrict__ Bc1, const float* __restrict__ Bc2,
    const float* __restrict__ resf32) {
    int lc = (li > NLIN - 1) ? (NLIN - 1) : li;   // JAX clamp semantics
    const float* Blbase = g_flags[0] ? Bc1 : Bc2;
    size_t bloff = (size_t)lc * D * RANK;

    __shared__ __half sA[2][BM][SSTR];
    __shared__ __half sB[2][BN][SSTR];

    int tid = threadIdx.x;
    int wid = tid >> 5, lane = tid & 31;
    int gid = lane >> 2, tig = lane & 3;
    int wm = wid & 3, wn = wid >> 2;
    int m0 = blockIdx.y * BM, n0 = blockIdx.x * BN;
    int scfl = g_flags[2];

    const __half c215 = __float2half(2.0f / 15.0f);
    const __half hone = __float2half(1.0f);

    float acc[2][8][4];
#pragma unroll
    for (int mi = 0; mi < 2; mi++)
#pragma unroll
        for (int ni = 0; ni < 8; ni++)
#pragma unroll
            for (int j = 0; j < 4; j++) acc[mi][ni][j] = 0.f;

    // staging registers
    float4 ar[4];   // XK==0: 16 f32
    int4   ah[2];   // XK!=0: 16 halves
    int4   br[4];   // 16 q ints
    __half scv;
    int dq_row = tid >> 1, dq_g = tid & 1;

    auto ldA = [&](int kt) {
        int k0 = kt * BK;
        if (XK == 0) {
#pragma unroll
            for (int i = 0; i < 4; i++) {
                int e = tid + i * 256;
                int r = e >> 3, c4 = e & 7;
                ar[i] = *(const float4*)(xf32 + (size_t)(m0 + r) * D + k0 + c4 * 4);
            }
        } else {
            const __half* src = (XK == 1) ? g_r1h : g_r2h;
#pragma unroll
            for (int i = 0; i < 2; i++) {
                int e = tid + i * 256;
                int r = e >> 2, c8 = e & 3;
                ah[i] = *(const int4*)(src + (size_t)(m0 + r) * D + k0 + c8 * 8);
            }
        }
    };
    auto stA = [&](int b) {
        if (XK == 0) {
#pragma unroll
            for (int i = 0; i < 4; i++) {
                int e = tid + i * 256;
                int r = e >> 3, c4 = e & 7;
                __half2* d = (__half2*)&sA[b][r][c4 * 4];
                d[0] = __floats2half2_rn(ar[i].x, ar[i].y);
                d[1] = __floats2half2_rn(ar[i].z, ar[i].w);
            }
        } else {
#pragma unroll
            for (int i = 0; i < 2; i++) {
                int e = tid + i * 256;
                int r = e >> 2, c8 = e & 3;
                *(int4*)&sA[b][r][c8 * 8] = ah[i];
            }
        }
    };
    auto ldB = [&](int kt) {
        int k0 = kt * BK;
        int row = n0 + dq_row;
        int colb = k0 + dq_g * 16;
        const int* qp = q + (size_t)lc * D * D + (size_t)row * D + colb;
#pragma unroll
        for (int i = 0; i < 4; i++) br[i] = *(const int4*)(qp + i * 4);
        scv = fetch_h(sc, (size_t)lc * D * (D / 16) + (size_t)row * (D / 16) + (colb >> 4),
                      (size_t)ns, scfl);
    };
    auto stB = [&](int b) {
#pragma unroll
        for (int v = 0; v < 4; v++) {
            __half w0 = __hmul(__hsub(__hmul(__int2half_rn(br[v].x), c215), hone), scv);
            __half w1 = __hmul(__hsub(__hmul(__int2half_rn(br[v].y), c215), hone), scv);
            __half w2 = __hmul(__hsub(__hmul(__int2half_rn(br[v].z), c215), hone), scv);
            __half w3 = __hmul(__hsub(__hmul(__int2half_rn(br[v].w), c215), hone), scv);
            int cb = dq_g * 16 + v * 4;
            *(__half2*)&sB[b][dq_row][cb]     = __halves2half2(w0, w1);
            *(__half2*)&sB[b][dq_row][cb + 2] = __halves2half2(w2, w3);
        }
    };

    // prologue
    ldA(0); ldB(0); stA(0); stB(0);
    __syncthreads();

    for (int kt = 0; kt < NT; ++kt) {
        int cur = kt & 1;
        if (kt + 1 < NT) { ldA(kt + 1); ldB(kt + 1); }
#pragma unroll
        for (int kk = 0; kk < 2; kk++) {
            int kb = kk * 16;
            uint32_t af[2][4], bf[8][2];
#pragma unroll
            for (int mi = 0; mi < 2; mi++) {
                int rb = wm * 32 + mi * 16;
                af[mi][0] = *(const uint32_t*)&sA[cur][rb + gid][kb + tig * 2];
                af[mi][1] = *(const uint32_t*)&sA[cur][rb + gid + 8][kb + tig * 2];
                af[mi][2] = *(const uint32_t*)&sA[cur][rb + gid][kb + tig * 2 + 8];
                af[mi][3] = *(const uint32_t*)&sA[cur][rb + gid + 8][kb + tig * 2 + 8];
            }
#pragma unroll
            for (int ni = 0; ni < 8; ni++) {
                int nb = wn * 64 + ni * 8 + gid;
                bf[ni][0] = *(const uint32_t*)&sB[cur][nb][kb + tig * 2];
                bf[ni][1] = *(const uint32_t*)&sB[cur][nb][kb + tig * 2 + 8];
            }
#pragma unroll
            for (int mi = 0; mi < 2; mi++)
#pragma unroll
                for (int ni = 0; ni < 8; ni++) mma16816(acc[mi][ni], af[mi], bf[ni]);
        }
        if (kt + 1 < NT) { stA(cur ^ 1); stB(cur ^ 1); }
        __syncthreads();
    }

    // f16-round + f16 bias (reference numerics), widen to f32
    {
        int fl = g_flags[3];
#pragma unroll
        for (int ni = 0; ni < 8; ni++) {
            int c0 = n0 + wn * 64 + ni * 8 + tig * 2;
            __half b0 = fetch_h(biases, (size_t)lc * D + c0, (size_t)nbias, fl);
            __half b1 = fetch_h(biases, (size_t)lc * D + c0 + 1, (size_t)nbias, fl);
#pragma unroll
            for (int mi = 0; mi < 2; mi++) {
                acc[mi][ni][0] = __half2float(__hadd(__float2half(acc[mi][ni][0]), b0));
                acc[mi][ni][1] = __half2float(__hadd(__float2half(acc[mi][ni][1]), b1));
                acc[mi][ni][2] = __half2float(__hadd(__float2half(acc[mi][ni][2]), b0));
                acc[mi][ni][3] = __half2float(__hadd(__float2half(acc[mi][ni][3]), b1));
            }
        }
    }

    // LoRA as 2 extra MMA k-steps: sA[0] <- sum of t partials, sB[0] <- 0.125*Bl
#pragma unroll
    for (int i = 0; i < 16; i++) {
        int e = tid + i * 256;
        int r = e >> 5, c = e & 31;
        size_t ti = (size_t)(m0 + r) * RANK + c;
        float tv = g_tp[ti] + g_tp[(size_t)MROWS * RANK + ti]
                 + g_tp[2 * (size_t)MROWS * RANK + ti]
                 + g_tp[3 * (size_t)MROWS * RANK + ti];
        sA[0][r][c] = __float2half(tv);
        sB[0][r][c] = __float2half(0.125f * Blbase[bloff + (size_t)(n0 + r) * RANK + c]);
    }
    __syncthreads();
#pragma unroll
    for (int kk = 0; kk < 2; kk++) {
        int kb = kk * 16;
        uint32_t af[2][4], bf[8][2];
#pragma unroll
        for (int mi = 0; mi < 2; mi++) {
            int rb = wm * 32 + mi * 16;
            af[mi][0] = *(const uint32_t*)&sA[0][rb + gid][kb + tig * 2];
            af[mi][1] = *(const uint32_t*)&sA[0][rb + gid + 8][kb + tig * 2];
            af[mi][2] = *(const uint32_t*)&sA[0][rb + gid][kb + tig * 2 + 8];
            af[mi][3] = *(const uint32_t*)&sA[0][rb + gid + 8][kb + tig * 2 + 8];
        }
#pragma unroll
        for (int ni = 0; ni < 8; ni++) {
            int nb = wn * 64 + ni * 8 + gid;
            bf[ni][0] = *(const uint32_t*)&sB[0][nb][kb + tig * 2];
            bf[ni][1] = *(const uint32_t*)&sB[0][nb][kb + tig * 2 + 8];
        }
#pragma unroll
        for (int mi = 0; mi < 2; mi++)
#pragma unroll
            for (int ni = 0; ni < 8; ni++) mma16816(acc[mi][ni], af[mi], bf[ni]);
    }

    // epilogue: residual / relu / store
#pragma unroll
    for (int mi = 0; mi < 2; mi++)
#pragma unroll
        for (int ni = 0; ni < 8; ni++) {
            int r0 = m0 + wm * 32 + mi * 16 + gid;
            int c0 = n0 + wn * 64 + ni * 8 + tig * 2;
#pragma unroll
            for (int h = 0; h < 2; h++) {
                int m = r0 + h * 8;
                float v0 = acc[mi][ni][h * 2], v1 = acc[mi][ni][h * 2 + 1];
                size_t gi = (size_t)m * D + c0;
                if (RESID) { v0 += resf32[gi]; v1 += resf32[gi + 1]; }
                if (RELU)  { v0 = fmaxf(v0, 0.f); v1 = fmaxf(v1, 0.f); }
                if (ysel == 1) {
                    g_r1h[gi] = __float2half(v0); g_r1h[gi + 1] = __float2half(v1);
                } else if (ysel == 2) {
                    g_r2h[gi] = __float2half(v0); g_r2h[gi + 1] = __float2half(v1);
                } else if ((long long)gi + 1 < nOut) {
                    out[gi] = v0; out[gi + 1] = v1;
                }
            }
        }
}

// ---------------- layernorm: warp per row, in-place on d_out ----------------
__global__ __launch_bounds__(256) void ln_kernel(float* out, long long nOut,
                                                 const float* __restrict__ gc1,
                                                 const float* __restrict__ gc2, int ng,
                                                 int blk) {
    const float* gbase = g_flags[1] ? gc2 : gc1;
    const float* bbase = g_flags[1] ? gc1 : gc2;
    int row = blockIdx.x * 8 + (threadIdx.x >> 5);
    int lane = threadIdx.x & 31;
    float v[32];
    float s = 0.f;
#pragma unroll
    for (int i = 0; i < 32; i++) {
        size_t gi = (size_t)row * D + lane + i * 32;
        v[i] = ((long long)gi < nOut) ? out[gi] : 0.f;
        s += v[i];
    }
#pragma unroll
    for (int off = 16; off > 0; off >>= 1) s += __shfl_xor_sync(0xffffffffu, s, off);
    float mu = s * (1.f / D);
    float ss = 0.f;
#pragma unroll
    for (int i = 0; i < 32; i++) { float d = v[i] - mu; ss += d * d; }
#pragma unroll
    for (int off = 16; off > 0; off >>= 1) ss += __shfl_xor_sync(0xffffffffu, ss, off);
    float inv = rsqrtf(ss * (1.f / D) + 1e-5f);
#pragma unroll
    for (int i = 0; i < 32; i++) {
        int c = lane + i * 32;
        size_t pi = (size_t)blk * D + c;
        float gg = gld(gbase, pi, (size_t)ng);
        float bb = gld(bbase, pi, (size_t)ng);
        size_t gi = (size_t)row * D + c;
        if ((long long)gi < nOut) out[gi] = (v[i] - mu) * inv * gg + bb;
    }
}

// ---------------- host launch ----------------
extern "C" void kernel_launch(void* const* d_in, const int* in_sizes, int n_in,
                              void* d_out, int out_size) {
    float* out = (float*)d_out;

    int ix = -1, iq = -1, is_ = -1, ib = -1, iA = -1, iB = -1, ig = -1, ib2 = -1;
    for (int i = 0; i < n_in; i++) {
        int sz = in_sizes[i];
        if      (sz == 8388608)  { if (ix < 0) ix = i; }
        else if (sz == 15728640) { if (iq < 0) iq = i; }
        else if (sz == 983040)   { if (is_ < 0) is_ = i; }
        else if (sz == 15360)    { if (ib < 0) ib = i; }
        else if (sz == 491520)   { if (iA < 0) iA = i; else if (iB < 0) iB = i; }
        else if (sz == 5120)     { if (ig < 0) ig = i; else if (ib2 < 0) ib2 = i; }
    }
    bool ok = (n_in >= 8) && ix >= 0 && iq >= 0 && is_ >= 0 && ib >= 0 &&
              iA >= 0 && iB >= 0 && ig >= 0 && ib2 >= 0;
    if (!ok) {
        int mask = (ix >= 0 ? 1 : 0) | (iq >= 0 ? 2 : 0) | (is_ >= 0 ? 4 : 0) |
                   (ib >= 0 ? 8 : 0) | ((iA >= 0 && iB >= 0) ? 16 : 0) |
                   ((ig >= 0 && ib2 >= 0) ? 32 : 0);
        float val = 1.0e6f * (float)n_in + 1000.0f * (float)mask;
        long long n = out_size;
        if (n > 8388608LL) n = 8388608LL;
        diag_kernel<<<(int)((n + 255) / 256), 256>>>(out, n, val);
        return;
    }

    const float* x      = (const float*)d_in[ix];
    const int*   qw     = (const int*)d_in[iq];
    const void*  scales = d_in[is_];
    const void*  biases = d_in[ib];
    const float* lA1    = (const float*)d_in[iA];
    const float* lA2    = (const float*)d_in[iB];
    const float* lg1    = (const float*)d_in[ig];
    const float* lg2    = (const float*)d_in[ib2];
    int nx = in_sizes[ix], ns = in_sizes[is_], nb = in_sizes[ib];
    int nA = in_sizes[iA], ng = in_sizes[ig];
    (void)nA;
    long long nOut = out_size;

    probe_kernel<<<1, 32>>>(lA1, lA2, lg1, lg2, scales, biases);

    dim3 ggrid(D / BN, MROWS / BM);      // (8, 64)
    dim3 lgrid(MROWS / BM, KSPLIT);      // (64, 4)

    int li = 0;
    for (int blk = 0; blk < 6; blk++) {
        int hsel = (blk == 0) ? -1 : 0;
        const float* hptr = (blk == 0) ? x : out;   // f32 residual-stream pointer
        // linear 0 (+relu): h -> r1h (f16)
        lora_t_kernel<<<lgrid, 256>>>(x, hsel, nx, out, lA1, lA2, li);
        gemm_kernel<0, true, false><<<ggrid, 256>>>(hptr, out, nOut, 1,
                                                    qw, scales, ns, biases, nb, li,
                                                    lA1, lA2, nullptr);
        li++;
        // linear 1 (+relu): r1h -> r2h (f16)
        lora_t_kernel<<<lgrid, 256>>>(x, 1, nx, out, lA1, lA2, li);
        gemm_kernel<1, true, false><<<ggrid, 256>>>(nullptr, out, nOut, 2,
                                                    qw, scales, ns, biases, nb, li,
                                                    lA1, lA2, nullptr);
        li++;
        // linear 2 (+block residual): r2h -> d_out (in-place resid add)
        lora_t_kernel<<<lgrid, 256>>>(x, 2, nx, out, lA1, lA2, li);
        gemm_kernel<2, false, true><<<ggrid, 256>>>(nullptr, out, nOut, 0,
                                                    qw, scales, ns, biases, nb, li,
                                                    lA1, lA2, hptr);
        li++;
        if (blk < 5) {
            ln_kernel<<<MROWS / 8, 256>>>(out, nOut, lg1, lg2, ng, blk);
        }
    }
}